// round 2
// baseline (speedup 1.0000x reference)
#include <cuda_runtime.h>
#include <cstdint>

#define VOCAB 50257
#define EMBED 256
#define HID   128
#define G4    512   // 4*HID
#define BATCH 128
#define SEQ   1024

#define LOG2E 1.4426950408889634f

// Gate-projection table: table[v][g] = sum_e emb[v][e]*W_ih[g][e] + b_ih[g]+b_hh[g]
__device__ float g_table[(size_t)VOCAB * G4];

// ---------------- packed fp32x2 helpers ----------------
__device__ __forceinline__ unsigned long long pack2(float lo, float hi) {
    unsigned long long r;
    asm("mov.b64 %0, {%1, %2};" : "=l"(r) : "f"(lo), "f"(hi));
    return r;
}
__device__ __forceinline__ unsigned long long splat2(float x) {
    unsigned long long r;
    asm("mov.b64 %0, {%1, %1};" : "=l"(r) : "f"(x));
    return r;
}
__device__ __forceinline__ void unpack2(unsigned long long v, float& lo, float& hi) {
    asm("mov.b64 {%0, %1}, %2;" : "=f"(lo), "=f"(hi) : "l"(v));
}
__device__ __forceinline__ void ffma2(unsigned long long& d, unsigned long long a, unsigned long long b) {
    asm("fma.rn.f32x2 %0, %1, %2, %0;" : "+l"(d) : "l"(a), "l"(b));
}
__device__ __forceinline__ float ex2f(float x) {
    float y; asm("ex2.approx.f32 %0, %1;" : "=f"(y) : "f"(x)); return y;
}
__device__ __forceinline__ float rcpf(float x) {
    float y; asm("rcp.approx.f32 %0, %1;" : "=f"(y) : "f"(x)); return y;
}
// branchless 4-way select
__device__ __forceinline__ float pick4(float v0, float v1, float v2, float v3, int d) {
    float a = (d & 1) ? v1 : v0;
    float b = (d & 1) ? v3 : v2;
    return (d & 2) ? b : a;
}

// =====================================================================
// Kernel 1: table[v][g] = emb[v] . W_ih[g] + bias[g]
// Tile: 128 vocab x 128 gates, 256 threads, 8x8 microtile, FFMA2.
// =====================================================================
#define TBM 128
#define TBN 128
#define TKC 16
#define TPAD 4

__global__ void __launch_bounds__(256) table_kernel(
    const float* __restrict__ emb,
    const float* __restrict__ W_ih,
    const float* __restrict__ b_ih,
    const float* __restrict__ b_hh)
{
    __shared__ float As[TKC][TBM + TPAD];   // transposed: As[k][v]
    __shared__ float Bs[TKC][TBN + TPAD];   // transposed: Bs[k][g]

    const int v0 = blockIdx.x * TBM;
    const int g0 = blockIdx.y * TBN;
    const int tid = threadIdx.x;
    const int ty = tid >> 4;     // 0..15  (vocab octet)
    const int tx = tid & 15;     // 0..15  (gate octet)

    const int arow = tid >> 1;          // 0..127
    const int acol = (tid & 1) * 8;     // 0 or 8 (k offset)

    unsigned long long acc[8][4];
#pragma unroll
    for (int i = 0; i < 8; i++)
#pragma unroll
        for (int p = 0; p < 4; p++) acc[i][p] = 0ull;

    const int vload = min(v0 + arow, VOCAB - 1);
    const int grow  = g0 + arow;

    for (int k0 = 0; k0 < EMBED; k0 += TKC) {
        // load A tile (emb rows), transpose into SMEM
        float4 a0 = *(const float4*)(emb + (size_t)vload * EMBED + k0 + acol);
        float4 a1 = *(const float4*)(emb + (size_t)vload * EMBED + k0 + acol + 4);
        As[acol + 0][arow] = a0.x; As[acol + 1][arow] = a0.y;
        As[acol + 2][arow] = a0.z; As[acol + 3][arow] = a0.w;
        As[acol + 4][arow] = a1.x; As[acol + 5][arow] = a1.y;
        As[acol + 6][arow] = a1.z; As[acol + 7][arow] = a1.w;
        // load B tile (W_ih rows), transpose into SMEM
        float4 b0 = *(const float4*)(W_ih + (size_t)grow * EMBED + k0 + acol);
        float4 b1 = *(const float4*)(W_ih + (size_t)grow * EMBED + k0 + acol + 4);
        Bs[acol + 0][arow] = b0.x; Bs[acol + 1][arow] = b0.y;
        Bs[acol + 2][arow] = b0.z; Bs[acol + 3][arow] = b0.w;
        Bs[acol + 4][arow] = b1.x; Bs[acol + 5][arow] = b1.y;
        Bs[acol + 6][arow] = b1.z; Bs[acol + 7][arow] = b1.w;
        __syncthreads();

#pragma unroll
        for (int k = 0; k < TKC; k++) {
            float4 bl = *(const float4*)&Bs[k][tx * 8];
            float4 bh = *(const float4*)&Bs[k][tx * 8 + 4];
            unsigned long long b2[4];
            b2[0] = pack2(bl.x, bl.y);
            b2[1] = pack2(bl.z, bl.w);
            b2[2] = pack2(bh.x, bh.y);
            b2[3] = pack2(bh.z, bh.w);
            float4 al = *(const float4*)&As[k][ty * 8];
            float4 ah = *(const float4*)&As[k][ty * 8 + 4];
            unsigned long long av[8];
            av[0] = splat2(al.x); av[1] = splat2(al.y);
            av[2] = splat2(al.z); av[3] = splat2(al.w);
            av[4] = splat2(ah.x); av[5] = splat2(ah.y);
            av[6] = splat2(ah.z); av[7] = splat2(ah.w);
#pragma unroll
            for (int i = 0; i < 8; i++)
#pragma unroll
                for (int p = 0; p < 4; p++)
                    ffma2(acc[i][p], av[i], b2[p]);
        }
        __syncthreads();
    }

    // epilogue: add bias, store
    const int gbase = g0 + tx * 8;
    float bz[8];
#pragma unroll
    for (int c = 0; c < 8; c++) bz[c] = b_ih[gbase + c] + b_hh[gbase + c];

#pragma unroll
    for (int i = 0; i < 8; i++) {
        int v = v0 + ty * 8 + i;
        if (v < VOCAB) {
            float r[8];
#pragma unroll
            for (int p = 0; p < 4; p++) {
                float lo, hi;
                unpack2(acc[i][p], lo, hi);
                r[2 * p]     = lo + bz[2 * p];
                r[2 * p + 1] = hi + bz[2 * p + 1];
            }
            float* dst = &g_table[(size_t)v * G4 + gbase];
            *(float4*)(dst)     = make_float4(r[0], r[1], r[2], r[3]);
            *(float4*)(dst + 4) = make_float4(r[4], r[5], r[6], r[7]);
        }
    }
}

// =====================================================================
// Kernel 2: per-batch LSTM recurrence. 128 CTAs x 512 threads.
// Thread = (unit j = tid>>2, k-quarter q = tid&3).
// Each thread: 4 gate-partials over k in [32q, 32q+32).
// Gates i,f,g weights in regs (48 f32x2 pairs); gate o weights in SMEM.
// Cross-q reduction via 3 shfl; 1 activation per lane; 1 barrier/step.
// =====================================================================
struct __align__(16) LstmSmem {
    ulonglong2 ws2[8][512];   // o-gate weights: [k-pair-pair][tid], 64 KB
    float hbuf[HID];          // current hidden state
    float hred[256];          // head scratch
    int   toks[SEQ];          // token ids for this batch row
};

__global__ void __launch_bounds__(512, 1) lstm_kernel(
    const void* __restrict__ xraw,
    const float* __restrict__ W_hh,
    const float* __restrict__ W_fc,
    const float* __restrict__ b_fc,
    float* __restrict__ out)
{
    extern __shared__ char smem_raw[];
    LstmSmem* S = (LstmSmem*)smem_raw;

    const int b = blockIdx.x;
    const int tid = threadIdx.x;
    const int j = tid >> 2;   // hidden unit 0..127
    const int q = tid & 3;    // k-quarter 0..3

    // --- detect whether x is stored as int64 or int32 ---
    bool is64;
    {
        const int* xi = (const int*)xraw;
        int val = xi[2 * (tid & 31) + 1];
        unsigned m = __ballot_sync(0xffffffffu, val != 0);
        is64 = (m == 0u);
    }

    // --- preload this batch row's tokens ---
    if (is64) {
        const long long* x64 = (const long long*)xraw;
        for (int i = tid; i < SEQ; i += 512) S->toks[i] = (int)x64[(size_t)b * SEQ + i];
    } else {
        const int* x32 = (const int*)xraw;
        for (int i = tid; i < SEQ; i += 512) S->toks[i] = x32[(size_t)b * SEQ + i];
    }

    // --- load weights: gates i,f,g -> regs (48 pairs), gate o -> SMEM ---
    unsigned long long wreg[48];
#pragma unroll
    for (int gi = 0; gi < 3; gi++) {
        const float4* src = (const float4*)(W_hh + (size_t)(gi * HID + j) * HID + q * 32);
#pragma unroll
        for (int m = 0; m < 8; m++) {
            float4 w = src[m];
            wreg[gi * 16 + 2 * m]     = pack2(w.x, w.y);
            wreg[gi * 16 + 2 * m + 1] = pack2(w.z, w.w);
        }
    }
    {
        const float4* src = (const float4*)(W_hh + (size_t)(3 * HID + j) * HID + q * 32);
#pragma unroll
        for (int m = 0; m < 8; m++) {
            float4 w = src[m];
            ulonglong2 v;
            v.x = pack2(w.x, w.y);
            v.y = pack2(w.z, w.w);
            S->ws2[m][tid] = v;
        }
    }

    if (tid < HID) S->hbuf[tid] = 0.0f;
    float c = 0.0f;
    // per-lane activation constants (gate q: 0=i sig, 1=f sig, 2=g tanh, 3=o sig)
    const float am = (q == 2) ? 2.0f : 1.0f;   // multiplier inside exp and on s
    const float ab = (q == 2) ? -1.0f : 0.0f;  // offset
    const float ae = -LOG2E * am;              // exp scale
    __syncthreads();

    const float* tab = (const float*)g_table;
    float xgq = tab[(size_t)S->toks[0] * G4 + q * HID + j];

    const ulonglong2* hp = (const ulonglong2*)(S->hbuf) + q * 8;  // this lane's 32-float slice

    for (int t = 0; t < SEQ; t++) {
        // ---- 4 independent gate-partial chains over this lane's k-slice ----
        unsigned long long acc0 = 0ull, acc1 = 0ull, acc2 = 0ull, acc3 = 0ull;
#pragma unroll
        for (int p8 = 0; p8 < 8; p8++) {
            ulonglong2 hv = hp[p8];
            ulonglong2 wv = S->ws2[p8][tid];
            ffma2(acc0, wreg[0 * 16 + 2 * p8],     hv.x);
            ffma2(acc1, wreg[1 * 16 + 2 * p8],     hv.x);
            ffma2(acc2, wreg[2 * 16 + 2 * p8],     hv.x);
            ffma2(acc3, wv.x,                      hv.x);
            ffma2(acc0, wreg[0 * 16 + 2 * p8 + 1], hv.y);
            ffma2(acc1, wreg[1 * 16 + 2 * p8 + 1], hv.y);
            ffma2(acc2, wreg[2 * 16 + 2 * p8 + 1], hv.y);
            ffma2(acc3, wv.y,                      hv.y);
        }

        // prefetch next step's table entry (independent of h)
        float xg_nxt = 0.0f;
        if (t + 1 < SEQ) xg_nxt = tab[(size_t)S->toks[t + 1] * G4 + q * HID + j];

        float p0, p1, p2, p3, lo, hi;
        unpack2(acc0, lo, hi); p0 = lo + hi;
        unpack2(acc1, lo, hi); p1 = lo + hi;
        unpack2(acc2, lo, hi); p2 = lo + hi;
        unpack2(acc3, lo, hi); p3 = lo + hi;

        // ---- reduce across q so lane q ends with full z of gate q ----
        float u1 = pick4(p0, p1, p2, p3, q ^ 1);
        float r1 = __shfl_xor_sync(0xffffffffu, u1, 1);
        float s0 = pick4(p0, p1, p2, p3, q) + r1;          // gate q, pairs {q,q^1}
        float u2 = pick4(p0, p1, p2, p3, q ^ 3);
        float r2 = __shfl_xor_sync(0xffffffffu, u2, 1);
        float s1 = pick4(p0, p1, p2, p3, q ^ 2) + r2;      // gate q^2, pairs {q,q^1}
        float z  = s0 + __shfl_xor_sync(0xffffffffu, s1, 2) + xgq;

        // ---- activation for this lane's gate (uniform sigmoid path) ----
        float e = ex2f(ae * z);
        float s = rcpf(1.0f + e);
        float a = fmaf(am, s, ab);   // sigmoid or tanh

        // ---- gather all four activations ----
        float a1 = __shfl_xor_sync(0xffffffffu, a, 1);   // gate q^1
        float a2 = __shfl_xor_sync(0xffffffffu, a, 2);   // gate q^2
        float a3 = __shfl_xor_sync(0xffffffffu, a1, 2);  // gate q^3
        float gi_ = pick4(a, a1, a2, a3, q);
        float gf_ = pick4(a, a1, a2, a3, q ^ 1);
        float gg_ = pick4(a, a1, a2, a3, q ^ 2);
        float go_ = pick4(a, a1, a2, a3, q ^ 3);

        // ---- cell/hidden update (bit-identical across the 4 lanes) ----
        c = fmaf(gf_, c, gi_ * gg_);
        float tc = fmaf(2.0f, rcpf(1.0f + ex2f(-2.0f * LOG2E * c)), -1.0f);
        float h = go_ * tc;
        if (q == 0) S->hbuf[j] = h;

        xgq = xg_nxt;
        __syncthreads();
    }

    // --- final linear head ---
    if (tid < 256) {
        int cls = tid >> 7;
        int jj  = tid & 127;
        S->hred[tid] = S->hbuf[jj] * W_fc[cls * HID + jj];
    }
    __syncthreads();
    if (tid < 2) {
        float s = b_fc[tid];
#pragma unroll 8
        for (int jj = 0; jj < HID; jj++) s += S->hred[tid * HID + jj];
        out[b * 2 + tid] = s;
    }
}

// =====================================================================
extern "C" void kernel_launch(void* const* d_in, const int* in_sizes, int n_in,
                              void* d_out, int out_size)
{
    const void*  x     = d_in[0];
    const float* emb   = (const float*)d_in[1];
    const float* W_ih  = (const float*)d_in[2];
    const float* W_hh  = (const float*)d_in[3];
    const float* b_ih  = (const float*)d_in[4];
    const float* b_hh  = (const float*)d_in[5];
    const float* W_fc  = (const float*)d_in[6];
    const float* b_fc  = (const float*)d_in[7];
    float* out = (float*)d_out;

    dim3 tgrid((VOCAB + TBM - 1) / TBM, G4 / TBN);   // 393 x 4
    table_kernel<<<tgrid, 256>>>(emb, W_ih, b_ih, b_hh);

    const int smem_bytes = (int)sizeof(LstmSmem);
    cudaFuncSetAttribute(lstm_kernel, cudaFuncAttributeMaxDynamicSharedMemorySize, smem_bytes);
    lstm_kernel<<<BATCH, 512, smem_bytes>>>(x, W_hh, W_fc, b_fc, out);
}

// round 3
// speedup vs baseline: 1.6652x; 1.6652x over previous
#include <cuda_runtime.h>
#include <cstdint>

#define VOCAB 50257
#define EMBED 256
#define HID   128
#define G4    512   // 4*HID
#define BATCH 128
#define SEQ   1024

#define LOG2E 1.4426950408889634f

// Gate-projection table: table[v][g] = sum_e emb[v][e]*W_ih[g][e] + b_ih[g]+b_hh[g]
__device__ float g_table[(size_t)VOCAB * G4];

typedef unsigned long long ull;

// ---------------- packed fp32x2 helpers ----------------
__device__ __forceinline__ ull pack2(float lo, float hi) {
    ull r; asm("mov.b64 %0, {%1, %2};" : "=l"(r) : "f"(lo), "f"(hi)); return r;
}
__device__ __forceinline__ ull splat2(float x) {
    ull r; asm("mov.b64 %0, {%1, %1};" : "=l"(r) : "f"(x)); return r;
}
__device__ __forceinline__ void unpack2(ull v, float& lo, float& hi) {
    asm("mov.b64 {%0, %1}, %2;" : "=f"(lo), "=f"(hi) : "l"(v));
}
__device__ __forceinline__ void ffma2(ull& d, ull a, ull b) {
    asm("fma.rn.f32x2 %0, %1, %2, %0;" : "+l"(d) : "l"(a), "l"(b));
}
__device__ __forceinline__ float ex2f(float x) {
    float y; asm("ex2.approx.f32 %0, %1;" : "=f"(y) : "f"(x)); return y;
}
__device__ __forceinline__ float rcpf(float x) {
    float y; asm("rcp.approx.f32 %0, %1;" : "=f"(y) : "f"(x)); return y;
}
// branchless 4-way select
__device__ __forceinline__ float pick4(float v0, float v1, float v2, float v3, int d) {
    float a = (d & 1) ? v1 : v0;
    float b = (d & 1) ? v3 : v2;
    return (d & 2) ? b : a;
}

// =====================================================================
// Kernel 1: table[v][g] = emb[v] . W_ih[g] + bias[g]
// 128x128 tile, 256 threads, 8x8 microtile, FFMA2, pre-packed SMEM:
//   As2: emb values stored SPLATTED as f32x2 ulls  -> no splat MOVs
//   Bs : plain floats, read as ulonglong2 (adjacent gate pairs) -> no pack MOVs
// =====================================================================
#define TBM 128
#define TBN 128
#define TKC 16
#define ASTRIDE (TBM + 2)   // ull stride (even -> 16B aligned rows)
#define BSTRIDE (TBN + 4)   // float stride (132 = 33*16B rows)

__global__ void __launch_bounds__(256, 2) table_kernel(
    const float* __restrict__ emb,
    const float* __restrict__ W_ih,
    const float* __restrict__ b_ih,
    const float* __restrict__ b_hh)
{
    __shared__ ull   As2[TKC][ASTRIDE];  // splatted emb: As2[k][v]
    __shared__ float Bs[TKC][BSTRIDE];   // W_ih transposed: Bs[k][g]

    const int v0 = blockIdx.x * TBM;
    const int g0 = blockIdx.y * TBN;
    const int tid = threadIdx.x;
    const int ty = tid >> 4;     // 0..15  (vocab octet)
    const int tx = tid & 15;     // 0..15  (gate octet)

    const int arow = tid >> 1;          // 0..127
    const int acol = (tid & 1) * 8;     // 0 or 8 (k offset)

    ull acc[8][4];
#pragma unroll
    for (int i = 0; i < 8; i++)
#pragma unroll
        for (int p = 0; p < 4; p++) acc[i][p] = 0ull;

    const int vload = min(v0 + arow, VOCAB - 1);
    const int grow  = g0 + arow;

    for (int k0 = 0; k0 < EMBED; k0 += TKC) {
        // load A tile (emb rows), splat+transpose into SMEM
        float4 a0 = *(const float4*)(emb + (size_t)vload * EMBED + k0 + acol);
        float4 a1 = *(const float4*)(emb + (size_t)vload * EMBED + k0 + acol + 4);
        As2[acol + 0][arow] = splat2(a0.x); As2[acol + 1][arow] = splat2(a0.y);
        As2[acol + 2][arow] = splat2(a0.z); As2[acol + 3][arow] = splat2(a0.w);
        As2[acol + 4][arow] = splat2(a1.x); As2[acol + 5][arow] = splat2(a1.y);
        As2[acol + 6][arow] = splat2(a1.z); As2[acol + 7][arow] = splat2(a1.w);
        // load B tile (W_ih rows), transpose into SMEM
        float4 b0 = *(const float4*)(W_ih + (size_t)grow * EMBED + k0 + acol);
        float4 b1 = *(const float4*)(W_ih + (size_t)grow * EMBED + k0 + acol + 4);
        Bs[acol + 0][arow] = b0.x; Bs[acol + 1][arow] = b0.y;
        Bs[acol + 2][arow] = b0.z; Bs[acol + 3][arow] = b0.w;
        Bs[acol + 4][arow] = b1.x; Bs[acol + 5][arow] = b1.y;
        Bs[acol + 6][arow] = b1.z; Bs[acol + 7][arow] = b1.w;
        __syncthreads();

#pragma unroll
        for (int k = 0; k < TKC; k++) {
            // B: 8 floats = 4 gate-pairs, directly as packed ulls
            ulonglong2 bp0 = *(const ulonglong2*)&Bs[k][tx * 8];
            ulonglong2 bp1 = *(const ulonglong2*)&Bs[k][tx * 8 + 4];
            ull b2[4] = { bp0.x, bp0.y, bp1.x, bp1.y };
            // A: 8 splatted values
            const ulonglong2* ap = (const ulonglong2*)&As2[k][ty * 8];
            ulonglong2 a01 = ap[0], a23 = ap[1], a45 = ap[2], a67 = ap[3];
            ull av[8] = { a01.x, a01.y, a23.x, a23.y, a45.x, a45.y, a67.x, a67.y };
#pragma unroll
            for (int i = 0; i < 8; i++)
#pragma unroll
                for (int p = 0; p < 4; p++)
                    ffma2(acc[i][p], av[i], b2[p]);
        }
        __syncthreads();
    }

    // epilogue: add bias, store
    const int gbase = g0 + tx * 8;
    float bz[8];
#pragma unroll
    for (int c = 0; c < 8; c++) bz[c] = b_ih[gbase + c] + b_hh[gbase + c];

#pragma unroll
    for (int i = 0; i < 8; i++) {
        int v = v0 + ty * 8 + i;
        if (v < VOCAB) {
            float r[8];
#pragma unroll
            for (int p = 0; p < 4; p++) {
                float lo, hi;
                unpack2(acc[i][p], lo, hi);
                r[2 * p]     = lo + bz[2 * p];
                r[2 * p + 1] = hi + bz[2 * p + 1];
            }
            float* dst = &g_table[(size_t)v * G4 + gbase];
            *(float4*)(dst)     = make_float4(r[0], r[1], r[2], r[3]);
            *(float4*)(dst + 4) = make_float4(r[4], r[5], r[6], r[7]);
        }
    }
}

// =====================================================================
// Kernel 2: per-batch LSTM recurrence. 128 CTAs x 512 threads.
// Thread = (unit j = tid>>2, k-quarter q = tid&3).
// acc_m at lane q accumulates gate (q^m)'s partial over k in [32q,32q+32):
//   -> reduction is pure shfl_xor with static register indices.
// Weights: acc0..2 gates in regs (48 f32x2); acc3 gate in SMEM.
// h stored skewed (slice q at float offset q*36 -> conflict-free) and
// double-buffered (no read/write race). One barrier per step.
// =====================================================================
#define HSKB 148   // floats per h buffer (4 slices of 36 + pad to 16B)

struct __align__(16) LstmSmem {
    ulonglong2 ws2[8][512];   // per-lane SMEM-gate weights, 64 KB
    float hsk[2][HSKB];       // double-buffered skewed h
    float hred[256];          // head scratch
    int   toks[SEQ];          // token ids for this batch row
};

__global__ void __launch_bounds__(512, 1) lstm_kernel(
    const void* __restrict__ xraw,
    const float* __restrict__ W_hh,
    const float* __restrict__ W_fc,
    const float* __restrict__ b_fc,
    float* __restrict__ out)
{
    extern __shared__ char smem_raw[];
    LstmSmem* S = (LstmSmem*)smem_raw;

    const int b = blockIdx.x;
    const int tid = threadIdx.x;
    const int j = tid >> 2;   // hidden unit 0..127
    const int q = tid & 3;    // k-quarter 0..3

    // --- detect whether x is stored as int64 or int32 ---
    bool is64;
    {
        const int* xi = (const int*)xraw;
        int val = xi[2 * (tid & 31) + 1];
        unsigned m = __ballot_sync(0xffffffffu, val != 0);
        is64 = (m == 0u);
    }

    // --- preload this batch row's tokens ---
    if (is64) {
        const long long* x64 = (const long long*)xraw;
        for (int i = tid; i < SEQ; i += 512) S->toks[i] = (int)x64[(size_t)b * SEQ + i];
    } else {
        const int* x32 = (const int*)xraw;
        for (int i = tid; i < SEQ; i += 512) S->toks[i] = x32[(size_t)b * SEQ + i];
    }

    // --- load weights. acc_m holds gate (q^m); gates q^0,q^1,q^2 -> regs, q^3 -> SMEM ---
    ull wreg[48];
#pragma unroll
    for (int m = 0; m < 3; m++) {
        const float4* src = (const float4*)(W_hh + (size_t)((q ^ m) * HID + j) * HID + q * 32);
#pragma unroll
        for (int u = 0; u < 8; u++) {
            float4 w = src[u];
            wreg[m * 16 + 2 * u]     = pack2(w.x, w.y);
            wreg[m * 16 + 2 * u + 1] = pack2(w.z, w.w);
        }
    }
    {
        const float4* src = (const float4*)(W_hh + (size_t)((q ^ 3) * HID + j) * HID + q * 32);
#pragma unroll
        for (int u = 0; u < 8; u++) {
            float4 w = src[u];
            ulonglong2 v;
            v.x = pack2(w.x, w.y);
            v.y = pack2(w.z, w.w);
            S->ws2[u][tid] = v;
        }
    }

    // zero both h buffers
    for (int i = tid; i < 2 * HSKB; i += 512) ((float*)S->hsk)[i] = 0.0f;

    float c = 0.0f;
    // per-lane activation constants (lane q's z is gate q: 0=i,1=f,3=o sigmoid; 2=g tanh)
    const float am = (q == 2) ? 2.0f : 1.0f;
    const float ab = (q == 2) ? -1.0f : 0.0f;
    const float ae = -LOG2E * am;
    const bool hwriter = (q == (j >> 5));          // this lane writes h_j into slice j>>5
    const int hwidx = q * 36 + (j & 31);
    __syncthreads();

    const float* tabq = (const float*)g_table + q * HID + j;
    float xgq = tabq[(size_t)S->toks[0] * G4];

#pragma unroll 2
    for (int t = 0; t < SEQ; t++) {
        // prefetch next step's table entry early (independent of h)
        float xg_nxt = 0.0f;
        if (t + 1 < SEQ) xg_nxt = tabq[(size_t)S->toks[t + 1] * G4];

        // ---- 4 gate-partial chains over this lane's 32-k slice ----
        const ulonglong2* hp = (const ulonglong2*)(S->hsk[t & 1] + q * 36);
        ull acc0 = 0ull, acc1 = 0ull, acc2 = 0ull, acc3 = 0ull;
#pragma unroll
        for (int p8 = 0; p8 < 8; p8++) {
            ulonglong2 hv = hp[p8];
            ulonglong2 wv = S->ws2[p8][tid];
            ffma2(acc0, wreg[2 * p8],          hv.x);
            ffma2(acc1, wreg[16 + 2 * p8],     hv.x);
            ffma2(acc2, wreg[32 + 2 * p8],     hv.x);
            ffma2(acc3, wv.x,                  hv.x);
            ffma2(acc0, wreg[2 * p8 + 1],      hv.y);
            ffma2(acc1, wreg[16 + 2 * p8 + 1], hv.y);
            ffma2(acc2, wreg[32 + 2 * p8 + 1], hv.y);
            ffma2(acc3, wv.y,                  hv.y);
        }

        float p0, p1, p2, p3, lo, hi;
        unpack2(acc0, lo, hi); p0 = lo + hi;   // gate q     over slice q
        unpack2(acc1, lo, hi); p1 = lo + hi;   // gate q^1   over slice q
        unpack2(acc2, lo, hi); p2 = lo + hi;   // gate q^2   over slice q
        unpack2(acc3, lo, hi); p3 = lo + hi;   // gate q^3   over slice q

        // ---- reduce: lane q ends with full z of gate q (static shfl pattern) ----
        float s0 = p0 + __shfl_xor_sync(0xffffffffu, p1, 1);   // gate q   over {q, q^1}
        float s1 = p2 + __shfl_xor_sync(0xffffffffu, p3, 1);   // gate q^2 over {q, q^1}
        float z  = s0 + __shfl_xor_sync(0xffffffffu, s1, 2) + xgq;

        // ---- activation for gate q (uniform sigmoid path) ----
        float e = ex2f(ae * z);
        float s = rcpf(1.0f + e);
        float a = fmaf(am, s, ab);   // sigmoid or tanh

        // ---- gather the four activations: arr[m] = act(gate q^m) ----
        float a1 = __shfl_xor_sync(0xffffffffu, a, 1);
        float a2 = __shfl_xor_sync(0xffffffffu, a, 2);
        float a3 = __shfl_xor_sync(0xffffffffu, a1, 2);
        float gi_ = pick4(a, a1, a2, a3, q);       // gate 0: m=q
        float gf_ = pick4(a, a1, a2, a3, q ^ 1);   // gate 1
        float gg_ = pick4(a, a1, a2, a3, q ^ 2);   // gate 2
        float go_ = pick4(a, a1, a2, a3, q ^ 3);   // gate 3

        // ---- cell/hidden update (identical across the 4 lanes of unit j) ----
        c = fmaf(gf_, c, gi_ * gg_);
        float tc = fmaf(2.0f, rcpf(1.0f + ex2f(-2.0f * LOG2E * c)), -1.0f);
        float h = go_ * tc;
        if (hwriter) S->hsk[(t + 1) & 1][hwidx] = h;

        xgq = xg_nxt;
        __syncthreads();
    }

    // --- final linear head (h(SEQ) lives in buffer 0) ---
    if (tid < 256) {
        int cls = tid >> 7;
        int jj  = tid & 127;
        float hv = S->hsk[0][(jj >> 5) * 36 + (jj & 31)];
        S->hred[tid] = hv * W_fc[cls * HID + jj];
    }
    __syncthreads();
    if (tid < 2) {
        float s = b_fc[tid];
#pragma unroll 8
        for (int jj = 0; jj < HID; jj++) s += S->hred[tid * HID + jj];
        out[b * 2 + tid] = s;
    }
}

// =====================================================================
extern "C" void kernel_launch(void* const* d_in, const int* in_sizes, int n_in,
                              void* d_out, int out_size)
{
    const void*  x     = d_in[0];
    const float* emb   = (const float*)d_in[1];
    const float* W_ih  = (const float*)d_in[2];
    const float* W_hh  = (const float*)d_in[3];
    const float* b_ih  = (const float*)d_in[4];
    const float* b_hh  = (const float*)d_in[5];
    const float* W_fc  = (const float*)d_in[6];
    const float* b_fc  = (const float*)d_in[7];
    float* out = (float*)d_out;

    dim3 tgrid((VOCAB + TBM - 1) / TBM, G4 / TBN);   // 393 x 4
    table_kernel<<<tgrid, 256>>>(emb, W_ih, b_ih, b_hh);

    const int smem_bytes = (int)sizeof(LstmSmem);
    cudaFuncSetAttribute(lstm_kernel, cudaFuncAttributeMaxDynamicSharedMemorySize, smem_bytes);
    lstm_kernel<<<BATCH, 512, smem_bytes>>>(x, W_hh, W_fc, b_fc, out);
}

// round 4
// speedup vs baseline: 1.7788x; 1.0682x over previous
#include <cuda_runtime.h>
#include <cstdint>

#define VOCAB 50257
#define EMBED 256
#define HID   128
#define G4    512   // 4*HID
#define BATCH 128
#define SEQ   1024

#define LOG2E 1.4426950408889634f

// Gate-projection table: table[v][g] = sum_e emb[v][e]*W_ih[g][e] + b_ih[g]+b_hh[g]
__device__ float g_table[(size_t)VOCAB * G4];

typedef unsigned long long ull;

// ---------------- packed fp32x2 helpers ----------------
__device__ __forceinline__ ull pack2(float lo, float hi) {
    ull r; asm("mov.b64 %0, {%1, %2};" : "=l"(r) : "f"(lo), "f"(hi)); return r;
}
__device__ __forceinline__ ull splat2(float x) {
    ull r; asm("mov.b64 %0, {%1, %1};" : "=l"(r) : "f"(x)); return r;
}
__device__ __forceinline__ void unpack2(ull v, float& lo, float& hi) {
    asm("mov.b64 {%0, %1}, %2;" : "=f"(lo), "=f"(hi) : "l"(v));
}
__device__ __forceinline__ void ffma2(ull& d, ull a, ull b) {
    asm("fma.rn.f32x2 %0, %1, %2, %0;" : "+l"(d) : "l"(a), "l"(b));
}
__device__ __forceinline__ float ex2f(float x) {
    float y; asm("ex2.approx.f32 %0, %1;" : "=f"(y) : "f"(x)); return y;
}
__device__ __forceinline__ float rcpf(float x) {
    float y; asm("rcp.approx.f32 %0, %1;" : "=f"(y) : "f"(x)); return y;
}

// =====================================================================
// Kernel 1: table[v][g] = emb[v] . W_ih[g] + bias[g]
// 128x128 tile, 256 threads, 8x8 microtile, FFMA2, pre-packed SMEM,
// GMEM->reg double-buffer prefetch to hide load latency.
// =====================================================================
#define TBM 128
#define TBN 128
#define TKC 16
#define ASTRIDE (TBM + 2)   // ull stride
#define BSTRIDE (TBN + 4)   // float stride
#define NK_ITERS (EMBED / TKC)   // 16

__global__ void __launch_bounds__(256, 2) table_kernel(
    const float* __restrict__ emb,
    const float* __restrict__ W_ih,
    const float* __restrict__ b_ih,
    const float* __restrict__ b_hh)
{
    __shared__ ull   As2[TKC][ASTRIDE];  // splatted emb: As2[k][v]
    __shared__ float Bs[TKC][BSTRIDE];   // W_ih transposed: Bs[k][g]

    const int v0 = blockIdx.x * TBM;
    const int g0 = blockIdx.y * TBN;
    const int tid = threadIdx.x;
    const int ty = tid >> 4;     // 0..15  (vocab octet)
    const int tx = tid & 15;     // 0..15  (gate octet)

    const int arow = tid >> 1;          // 0..127
    const int acol = (tid & 1) * 8;     // 0 or 8 (k offset)

    ull acc[8][4];
#pragma unroll
    for (int i = 0; i < 8; i++)
#pragma unroll
        for (int p = 0; p < 4; p++) acc[i][p] = 0ull;

    const int vload = min(v0 + arow, VOCAB - 1);
    const int grow  = g0 + arow;
    const float* aptr = emb  + (size_t)vload * EMBED + acol;
    const float* bptr = W_ih + (size_t)grow  * EMBED + acol;

    // prefetch iteration 0
    float4 ra0 = *(const float4*)(aptr);
    float4 ra1 = *(const float4*)(aptr + 4);
    float4 rb0 = *(const float4*)(bptr);
    float4 rb1 = *(const float4*)(bptr + 4);

    for (int it = 0; it < NK_ITERS; it++) {
        // store current tile into SMEM
        As2[acol + 0][arow] = splat2(ra0.x); As2[acol + 1][arow] = splat2(ra0.y);
        As2[acol + 2][arow] = splat2(ra0.z); As2[acol + 3][arow] = splat2(ra0.w);
        As2[acol + 4][arow] = splat2(ra1.x); As2[acol + 5][arow] = splat2(ra1.y);
        As2[acol + 6][arow] = splat2(ra1.z); As2[acol + 7][arow] = splat2(ra1.w);
        Bs[acol + 0][arow] = rb0.x; Bs[acol + 1][arow] = rb0.y;
        Bs[acol + 2][arow] = rb0.z; Bs[acol + 3][arow] = rb0.w;
        Bs[acol + 4][arow] = rb1.x; Bs[acol + 5][arow] = rb1.y;
        Bs[acol + 6][arow] = rb1.z; Bs[acol + 7][arow] = rb1.w;
        __syncthreads();

        // issue next tile's GMEM loads (clamped; latency hidden under compute)
        {
            int knext = min((it + 1) * TKC, EMBED - TKC);
            ra0 = *(const float4*)(aptr + knext);
            ra1 = *(const float4*)(aptr + knext + 4);
            rb0 = *(const float4*)(bptr + knext);
            rb1 = *(const float4*)(bptr + knext + 4);
        }

#pragma unroll
        for (int k = 0; k < TKC; k++) {
            ulonglong2 bp0 = *(const ulonglong2*)&Bs[k][tx * 8];
            ulonglong2 bp1 = *(const ulonglong2*)&Bs[k][tx * 8 + 4];
            ull b2[4] = { bp0.x, bp0.y, bp1.x, bp1.y };
            const ulonglong2* ap = (const ulonglong2*)&As2[k][ty * 8];
            ulonglong2 a01 = ap[0], a23 = ap[1], a45 = ap[2], a67 = ap[3];
            ull av[8] = { a01.x, a01.y, a23.x, a23.y, a45.x, a45.y, a67.x, a67.y };
#pragma unroll
            for (int i = 0; i < 8; i++)
#pragma unroll
                for (int p = 0; p < 4; p++)
                    ffma2(acc[i][p], av[i], b2[p]);
        }
        __syncthreads();
    }

    // epilogue: add bias, store
    const int gbase = g0 + tx * 8;
    float bz[8];
#pragma unroll
    for (int c = 0; c < 8; c++) bz[c] = b_ih[gbase + c] + b_hh[gbase + c];

#pragma unroll
    for (int i = 0; i < 8; i++) {
        int v = v0 + ty * 8 + i;
        if (v < VOCAB) {
            float r[8];
#pragma unroll
            for (int p = 0; p < 4; p++) {
                float lo, hi;
                unpack2(acc[i][p], lo, hi);
                r[2 * p]     = lo + bz[2 * p];
                r[2 * p + 1] = hi + bz[2 * p + 1];
            }
            float* dst = &g_table[(size_t)v * G4 + gbase];
            *(float4*)(dst)     = make_float4(r[0], r[1], r[2], r[3]);
            *(float4*)(dst + 4) = make_float4(r[4], r[5], r[6], r[7]);
        }
    }
}

// =====================================================================
// Kernel 2: per-batch LSTM recurrence. 128 CTAs x 512 threads.
// Thread = (unit j = tid>>2, k-quarter q = tid&3).
// acc_m at lane q accumulates gate (q^m) over k in [32q,32q+32).
// Gates q^0..q^2 weights in regs; gate q^3 in SMEM, loads software-
// pipelined depth-2 (time-invariant values preload the next step too).
// h skewed + double-buffered. One barrier per step.
// =====================================================================
#define HSKB 148   // floats per h buffer (4 slices of 36 + pad)

struct __align__(16) LstmSmem {
    ulonglong2 ws2[8][512];   // SMEM-gate weights, 64 KB
    float hsk[2][HSKB];       // double-buffered skewed h
    float hred[256];          // head scratch
    int   toff[SEQ + 2];      // token BYTE offsets into g_table (padded)
};

__global__ void __launch_bounds__(512, 1) lstm_kernel(
    const void* __restrict__ xraw,
    const float* __restrict__ W_hh,
    const float* __restrict__ W_fc,
    const float* __restrict__ b_fc,
    float* __restrict__ out)
{
    extern __shared__ char smem_raw[];
    LstmSmem* S = (LstmSmem*)smem_raw;

    const int b = blockIdx.x;
    const int tid = threadIdx.x;
    const int j = tid >> 2;   // hidden unit 0..127
    const int q = tid & 3;    // k-quarter 0..3

    // --- detect whether x is stored as int64 or int32 ---
    bool is64;
    {
        const int* xi = (const int*)xraw;
        int val = xi[2 * (tid & 31) + 1];
        unsigned m = __ballot_sync(0xffffffffu, val != 0);
        is64 = (m == 0u);
    }

    // --- preload token byte-offsets (tok * G4 * 4 bytes), pad last ---
    if (is64) {
        const long long* x64 = (const long long*)xraw + (size_t)b * SEQ;
        for (int i = tid; i <= SEQ; i += 512) {
            int src = min(i, SEQ - 1);
            S->toff[i] = ((int)x64[src]) << 11;   // *2048 bytes per row
        }
    } else {
        const int* x32 = (const int*)xraw + (size_t)b * SEQ;
        for (int i = tid; i <= SEQ; i += 512) {
            int src = min(i, SEQ - 1);
            S->toff[i] = x32[src] << 11;
        }
    }

    // --- load weights. acc_m holds gate (q^m); q^0..q^2 -> regs, q^3 -> SMEM ---
    ull wreg[48];
#pragma unroll
    for (int m = 0; m < 3; m++) {
        const float4* src = (const float4*)(W_hh + (size_t)((q ^ m) * HID + j) * HID + q * 32);
#pragma unroll
        for (int u = 0; u < 8; u++) {
            float4 w = src[u];
            wreg[m * 16 + 2 * u]     = pack2(w.x, w.y);
            wreg[m * 16 + 2 * u + 1] = pack2(w.z, w.w);
        }
    }
    {
        const float4* src = (const float4*)(W_hh + (size_t)((q ^ 3) * HID + j) * HID + q * 32);
#pragma unroll
        for (int u = 0; u < 8; u++) {
            float4 w = src[u];
            ulonglong2 v;
            v.x = pack2(w.x, w.y);
            v.y = pack2(w.z, w.w);
            S->ws2[u][tid] = v;
        }
    }

    // zero both h buffers
    for (int i = tid; i < 2 * HSKB; i += 512) ((float*)S->hsk)[i] = 0.0f;

    float c = 0.0f;
    // lane q's z is gate q: 0=i,1=f,3=o sigmoid; 2=g tanh (as 2*sig(2z)-1)
    const float am = (q == 2) ? 2.0f : 1.0f;
    const float ab = (q == 2) ? -1.0f : 0.0f;
    const float ae = -LOG2E * am;
    const bool hwriter = (q == (j >> 5));
    const int hwidx = q * 36 + (j & 31);
    __syncthreads();

    const char* tabq = (const char*)g_table + (size_t)(q * HID + j) * 4;
    float xgq = *(const float*)(tabq + S->toff[0]);

    const ulonglong2* hp0 = (const ulonglong2*)(S->hsk[0] + q * 36);
    const ulonglong2* hp1 = (const ulonglong2*)(S->hsk[1] + q * 36);
    const ulonglong2* wsp = &S->ws2[0][tid];   // stride between p8 rows = 512 ulonglong2

    // prime the depth-2 ws2 register ring
    ulonglong2 wvA = wsp[0 * 512];
    ulonglong2 wvB = wsp[1 * 512];

#pragma unroll 2
    for (int t = 0; t < SEQ; t++) {
        const ulonglong2* hp = (t & 1) ? hp1 : hp0;

        // prefetch next step's table entry (independent of h)
        float xg_nxt = *(const float*)(tabq + S->toff[t + 1]);

        // ---- 4 gate-partial chains; ws2 loads pipelined 2 ahead ----
        ull acc0 = 0ull, acc1 = 0ull, acc2 = 0ull, acc3 = 0ull;
#pragma unroll
        for (int p8 = 0; p8 < 8; p8++) {
            ulonglong2 hv = hp[p8];
            ffma2(acc0, wreg[2 * p8],          hv.x);
            ffma2(acc1, wreg[16 + 2 * p8],     hv.x);
            ffma2(acc2, wreg[32 + 2 * p8],     hv.x);
            ffma2(acc3, wvA.x,                 hv.x);
            ffma2(acc0, wreg[2 * p8 + 1],      hv.y);
            ffma2(acc1, wreg[16 + 2 * p8 + 1], hv.y);
            ffma2(acc2, wreg[32 + 2 * p8 + 1], hv.y);
            ffma2(acc3, wvA.y,                 hv.y);
            wvA = wvB;
            wvB = wsp[((p8 + 2) & 7) * 512];   // p8=6,7 reload rows 0,1 for NEXT step
        }

        float p0, p1, p2, p3, lo, hi;
        unpack2(acc0, lo, hi); p0 = lo + hi;
        unpack2(acc1, lo, hi); p1 = lo + hi;
        unpack2(acc2, lo, hi); p2 = lo + hi;
        unpack2(acc3, lo, hi); p3 = lo + hi;

        // ---- reduce: lane q ends with full z of gate q ----
        float s0 = p0 + __shfl_xor_sync(0xffffffffu, p1, 1);
        float s1 = p2 + __shfl_xor_sync(0xffffffffu, p3, 1);
        float z  = s0 + __shfl_xor_sync(0xffffffffu, s1, 2) + xgq;

        // ---- activation for gate q (uniform sigmoid path) ----
        float e = ex2f(ae * z);
        float s = rcpf(1.0f + e);
        float a = fmaf(am, s, ab);

        // ---- gather the four activations by absolute lane (width=4) ----
        float gi_ = __shfl_sync(0xffffffffu, a, 0, 4);
        float gf_ = __shfl_sync(0xffffffffu, a, 1, 4);
        float gg_ = __shfl_sync(0xffffffffu, a, 2, 4);
        float go_ = __shfl_sync(0xffffffffu, a, 3, 4);

        // ---- cell/hidden update (identical across the 4 lanes of unit j) ----
        c = fmaf(gf_, c, gi_ * gg_);
        float tc = fmaf(2.0f, rcpf(1.0f + ex2f(-2.0f * LOG2E * c)), -1.0f);
        float h = go_ * tc;
        if (hwriter) S->hsk[(t + 1) & 1][hwidx] = h;

        xgq = xg_nxt;
        __syncthreads();
    }

    // --- final linear head (h(SEQ) lives in buffer 0 since SEQ is even) ---
    if (tid < 256) {
        int cls = tid >> 7;
        int jj  = tid & 127;
        float hv = S->hsk[0][(jj >> 5) * 36 + (jj & 31)];
        S->hred[tid] = hv * W_fc[cls * HID + jj];
    }
    __syncthreads();
    if (tid < 2) {
        float s = b_fc[tid];
#pragma unroll 8
        for (int jj = 0; jj < HID; jj++) s += S->hred[tid * HID + jj];
        out[b * 2 + tid] = s;
    }
}

// =====================================================================
extern "C" void kernel_launch(void* const* d_in, const int* in_sizes, int n_in,
                              void* d_out, int out_size)
{
    const void*  x     = d_in[0];
    const float* emb   = (const float*)d_in[1];
    const float* W_ih  = (const float*)d_in[2];
    const float* W_hh  = (const float*)d_in[3];
    const float* b_ih  = (const float*)d_in[4];
    const float* b_hh  = (const float*)d_in[5];
    const float* W_fc  = (const float*)d_in[6];
    const float* b_fc  = (const float*)d_in[7];
    float* out = (float*)d_out;

    dim3 tgrid((VOCAB + TBM - 1) / TBM, G4 / TBN);   // 393 x 4
    table_kernel<<<tgrid, 256>>>(emb, W_ih, b_ih, b_hh);

    const int smem_bytes = (int)sizeof(LstmSmem);
    cudaFuncSetAttribute(lstm_kernel, cudaFuncAttributeMaxDynamicSharedMemorySize, smem_bytes);
    lstm_kernel<<<BATCH, 512, smem_bytes>>>(x, W_hh, W_fc, b_fc, out);
}